// round 6
// baseline (speedup 1.0000x reference)
#include <cuda_runtime.h>
#include <math.h>

// PINN forward + forward-mode JVPs (T, dT/dz, dT/dt, d2T/dz2)
// MLP: 3 -> 128 -> 128 -> 64 -> 1, tanh activations.
//
// R6: FFMA2 with minimized non-FMA issue slots.
//  - 64 points/block, 2 ADJACENT points per thread: both points' packed
//    activation pairs load with a single LDS.128 (2 per k instead of 4
//    LDS.64), conflict-free.
//  - Weights pre-DUPLICATED {w,w} in shared memory: no per-k pack MOVs;
//    4 warp-uniform LDS.128 per k. W2dup (128KB) staged in two 64KB
//    chunks (sync between half-k loops); W3dup (64KB) reuses the buffer.
//  - Activations in-place (epilogue in regs + syncs). Total smem 192KB.

#define TPB 512
#define PTS 64           // points per block (2 adjacent per thread)
#define H1  128
#define H2  128
#define H3  64

typedef unsigned long long ull;

__device__ __forceinline__ ull ffma2(ull a, ull b, ull c) {
    ull d;
    asm("fma.rn.f32x2 %0, %1, %2, %3;" : "=l"(d) : "l"(a), "l"(b), "l"(c));
    return d;
}
__device__ __forceinline__ ull pack2(float lo, float hi) {
    ull v;
    asm("mov.b64 %0, {%1, %2};" : "=l"(v) : "f"(lo), "f"(hi));
    return v;
}
__device__ __forceinline__ float2 unpack2(ull v) {
    float2 r;
    asm("mov.b64 {%0, %1}, %2;" : "=f"(r.x), "=f"(r.y) : "l"(v));
    return r;
}
// branch-free tanh: 1 - 2/(exp(2u)+1); exact limits at +-inf.
__device__ __forceinline__ float fast_tanh(float u) {
    float e, r;
    asm("ex2.approx.f32 %0, %1;" : "=f"(e) : "f"(u * 2.8853900817779268f));
    asm("rcp.approx.f32 %0, %1;" : "=f"(r) : "f"(e + 1.0f));
    return fmaf(-2.0f, r, 1.0f);
}
// tanh JVP epilogue on packed pairs.
__device__ __forceinline__ void tanh_jvp(ull u01, ull u23, ull* h01, ull* h23) {
    float2 v01 = unpack2(u01);   // x=u, y=u_dz
    float2 v23 = unpack2(u23);   // x=u_dt, y=u_dzz
    float h = fast_tanh(v01.x);
    float s = 1.0f - h * h;
    float hdz  = s * v01.y;
    float hdt  = s * v23.x;
    float hdzz = fmaf(-2.0f * h * hdz, v01.y, s * v23.y);
    *h01 = pack2(h, hdz);
    *h23 = pack2(hdt, hdzz);
}

__global__ __launch_bounds__(TPB, 1)
void pinn_fused_kernel(const float* __restrict__ x,
                       const float* __restrict__ W1, const float* __restrict__ b1,
                       const float* __restrict__ W2, const float* __restrict__ b2,
                       const float* __restrict__ W3, const float* __restrict__ b3,
                       const float* __restrict__ W4, const float* __restrict__ b4,
                       float* __restrict__ out)
{
    extern __shared__ float smem[];
    // A: {h,hdz}[128 units][64 pts] float2  = 64KB
    // B: {hdt,hdzz}[128][64] float2         = 64KB
    // Wdup: 8192 ull = 64KB (W2 chunk of 64 rows, or full W3dup)
    float2* A    = (float2*)smem;                 // 64KB
    float2* B    = A + H1 * PTS;                  // 64KB
    ull*    Wdup = (ull*)(B + H1 * PTS);          // 64KB

    const int tid  = threadIdx.x;
    const int lane = tid & 31;
    const int blk  = blockIdx.x;

    // -------- stage W2dup chunk 0 (rows 0..63) --------
    {
        const float4* src = (const float4*)W2;
        #pragma unroll
        for (int it = 0; it < (64 * H2 / 4) / TPB; it++) {
            int i = tid + it * TPB;
            float4 w = __ldg(&src[i]);
            ull* d = Wdup + i * 4;
            d[0] = pack2(w.x, w.x);  d[1] = pack2(w.y, w.y);
            d[2] = pack2(w.z, w.z);  d[3] = pack2(w.w, w.w);
        }
    }

    // ---------------- Layer 1: 3 -> 128 (K=3 direct) ----------------
    #pragma unroll
    for (int it = 0; it < (PTS * H1) / TPB; it++) {
        int idx = tid + it * TPB;
        int pp = idx & (PTS - 1);
        int j  = idx / PTS;
        int pg = blk * PTS + pp;
        float x0 = x[pg * 3 + 0];
        float x1 = x[pg * 3 + 1];
        float x2 = x[pg * 3 + 2];
        float w0 = __ldg(&W1[j]);
        float w1 = __ldg(&W1[H1 + j]);
        float w2 = __ldg(&W1[2 * H1 + j]);
        float u  = fmaf(x0, w0, fmaf(x1, w1, fmaf(x2, w2, __ldg(&b1[j]))));
        float h  = fast_tanh(u);
        float s  = 1.0f - h * h;
        float hdz  = s * w0;
        float hdt  = s * w1;
        float hdzz = -2.0f * h * hdz * w0;
        A[j * PTS + pp] = make_float2(h, hdz);
        B[j * PTS + pp] = make_float2(hdt, hdzz);
    }
    __syncthreads();

    // ---------------- Layer 2: 128 -> 128 (in-place, 2 weight chunks) ----
    // 16 warps x 8 cols; thread owns adjacent points (2*lane, 2*lane+1).
    {
        const int j0 = (tid >> 5) * 8;
        ull acc01a[8], acc23a[8], acc01b[8], acc23b[8];
        #pragma unroll
        for (int c = 0; c < 8; c++) {
            ull bias = pack2(b2[j0 + c], 0.0f);
            acc01a[c] = bias;  acc01b[c] = bias;
            acc23a[c] = 0ULL;  acc23b[c] = 0ULL;
        }
        const ulonglong2* aAp = (const ulonglong2*)((const ull*)A + 2 * lane);
        const ulonglong2* aBp = (const ulonglong2*)((const ull*)B + 2 * lane);

        #pragma unroll 1
        for (int chunk = 0; chunk < 2; chunk++) {
            #pragma unroll 4
            for (int kk = 0; kk < 64; kk++) {
                int k = chunk * 64 + kk;
                ulonglong2 a01 = aAp[k * (PTS / 2)];   // {h,hdz} pts p0,p1
                ulonglong2 a23 = aBp[k * (PTS / 2)];   // {hdt,hdzz} pts p0,p1
                const ulonglong2* wr = (const ulonglong2*)(Wdup + kk * H2 + j0);
                ulonglong2 wA = wr[0], wB = wr[1], wC = wr[2], wD = wr[3];
                acc01a[0] = ffma2(a01.x, wA.x, acc01a[0]);  acc23a[0] = ffma2(a23.x, wA.x, acc23a[0]);
                acc01b[0] = ffma2(a01.y, wA.x, acc01b[0]);  acc23b[0] = ffma2(a23.y, wA.x, acc23b[0]);
                acc01a[1] = ffma2(a01.x, wA.y, acc01a[1]);  acc23a[1] = ffma2(a23.x, wA.y, acc23a[1]);
                acc01b[1] = ffma2(a01.y, wA.y, acc01b[1]);  acc23b[1] = ffma2(a23.y, wA.y, acc23b[1]);
                acc01a[2] = ffma2(a01.x, wB.x, acc01a[2]);  acc23a[2] = ffma2(a23.x, wB.x, acc23a[2]);
                acc01b[2] = ffma2(a01.y, wB.x, acc01b[2]);  acc23b[2] = ffma2(a23.y, wB.x, acc23b[2]);
                acc01a[3] = ffma2(a01.x, wB.y, acc01a[3]);  acc23a[3] = ffma2(a23.x, wB.y, acc23a[3]);
                acc01b[3] = ffma2(a01.y, wB.y, acc01b[3]);  acc23b[3] = ffma2(a23.y, wB.y, acc23b[3]);
                acc01a[4] = ffma2(a01.x, wC.x, acc01a[4]);  acc23a[4] = ffma2(a23.x, wC.x, acc23a[4]);
                acc01b[4] = ffma2(a01.y, wC.x, acc01b[4]);  acc23b[4] = ffma2(a23.y, wC.x, acc23b[4]);
                acc01a[5] = ffma2(a01.x, wC.y, acc01a[5]);  acc23a[5] = ffma2(a23.x, wC.y, acc23a[5]);
                acc01b[5] = ffma2(a01.y, wC.y, acc01b[5]);  acc23b[5] = ffma2(a23.y, wC.y, acc23b[5]);
                acc01a[6] = ffma2(a01.x, wD.x, acc01a[6]);  acc23a[6] = ffma2(a23.x, wD.x, acc23a[6]);
                acc01b[6] = ffma2(a01.y, wD.x, acc01b[6]);  acc23b[6] = ffma2(a23.y, wD.x, acc23b[6]);
                acc01a[7] = ffma2(a01.x, wD.y, acc01a[7]);  acc23a[7] = ffma2(a23.x, wD.y, acc23a[7]);
                acc01b[7] = ffma2(a01.y, wD.y, acc01b[7]);  acc23b[7] = ffma2(a23.y, wD.y, acc23b[7]);
            }
            if (chunk == 0) {
                // restage Wdup with rows 64..127
                __syncthreads();
                const float4* src = (const float4*)(W2 + 64 * H2);
                #pragma unroll
                for (int it = 0; it < (64 * H2 / 4) / TPB; it++) {
                    int i = tid + it * TPB;
                    float4 w = __ldg(&src[i]);
                    ull* d = Wdup + i * 4;
                    d[0] = pack2(w.x, w.x);  d[1] = pack2(w.y, w.y);
                    d[2] = pack2(w.z, w.z);  d[3] = pack2(w.w, w.w);
                }
                __syncthreads();
            }
        }
        // epilogue in registers
        ull h01a[8], h23a[8], h01b[8], h23b[8];
        #pragma unroll
        for (int c = 0; c < 8; c++) {
            tanh_jvp(acc01a[c], acc23a[c], &h01a[c], &h23a[c]);
            tanh_jvp(acc01b[c], acc23b[c], &h01b[c], &h23b[c]);
        }
        __syncthreads();   // all reads of layer-1 activations done
        #pragma unroll
        for (int c = 0; c < 8; c++) {
            int j = j0 + c;
            ulonglong2* oA = (ulonglong2*)((ull*)A + j * PTS + 2 * lane);
            ulonglong2* oB = (ulonglong2*)((ull*)B + j * PTS + 2 * lane);
            *oA = make_ulonglong2(h01a[c], h01b[c]);
            *oB = make_ulonglong2(h23a[c], h23b[c]);
        }
    }
    __syncthreads();

    // -------- stage W3dup (full 128x64 = 64KB) --------
    {
        const float4* src = (const float4*)W3;
        #pragma unroll
        for (int it = 0; it < (H2 * H3 / 4) / TPB; it++) {
            int i = tid + it * TPB;
            float4 w = __ldg(&src[i]);
            ull* d = Wdup + i * 4;
            d[0] = pack2(w.x, w.x);  d[1] = pack2(w.y, w.y);
            d[2] = pack2(w.z, w.z);  d[3] = pack2(w.w, w.w);
        }
    }
    __syncthreads();

    // ---------------- Layer 3: 128 -> 64 (in-place) ----------------
    // 16 warps x 4 cols; adjacent points per thread.
    {
        const int j0 = (tid >> 5) * 4;
        ull acc01a[4], acc23a[4], acc01b[4], acc23b[4];
        #pragma unroll
        for (int c = 0; c < 4; c++) {
            ull bias = pack2(b3[j0 + c], 0.0f);
            acc01a[c] = bias;  acc01b[c] = bias;
            acc23a[c] = 0ULL;  acc23b[c] = 0ULL;
        }
        const ulonglong2* aAp = (const ulonglong2*)((const ull*)A + 2 * lane);
        const ulonglong2* aBp = (const ulonglong2*)((const ull*)B + 2 * lane);
        #pragma unroll 4
        for (int k = 0; k < H2; k++) {
            ulonglong2 a01 = aAp[k * (PTS / 2)];
            ulonglong2 a23 = aBp[k * (PTS / 2)];
            const ulonglong2* wr = (const ulonglong2*)(Wdup + k * H3 + j0);
            ulonglong2 wA = wr[0], wB = wr[1];
            acc01a[0] = ffma2(a01.x, wA.x, acc01a[0]);  acc23a[0] = ffma2(a23.x, wA.x, acc23a[0]);
            acc01b[0] = ffma2(a01.y, wA.x, acc01b[0]);  acc23b[0] = ffma2(a23.y, wA.x, acc23b[0]);
            acc01a[1] = ffma2(a01.x, wA.y, acc01a[1]);  acc23a[1] = ffma2(a23.x, wA.y, acc23a[1]);
            acc01b[1] = ffma2(a01.y, wA.y, acc01b[1]);  acc23b[1] = ffma2(a23.y, wA.y, acc23b[1]);
            acc01a[2] = ffma2(a01.x, wB.x, acc01a[2]);  acc23a[2] = ffma2(a23.x, wB.x, acc23a[2]);
            acc01b[2] = ffma2(a01.y, wB.x, acc01b[2]);  acc23b[2] = ffma2(a23.y, wB.x, acc23b[2]);
            acc01a[3] = ffma2(a01.x, wB.y, acc01a[3]);  acc23a[3] = ffma2(a23.x, wB.y, acc23a[3]);
            acc01b[3] = ffma2(a01.y, wB.y, acc01b[3]);  acc23b[3] = ffma2(a23.y, wB.y, acc23b[3]);
        }
        ull h01a[4], h23a[4], h01b[4], h23b[4];
        #pragma unroll
        for (int c = 0; c < 4; c++) {
            tanh_jvp(acc01a[c], acc23a[c], &h01a[c], &h23a[c]);
            tanh_jvp(acc01b[c], acc23b[c], &h01b[c], &h23b[c]);
        }
        __syncthreads();   // all reads of layer-2 activations done
        #pragma unroll
        for (int c = 0; c < 4; c++) {
            int j = j0 + c;
            ulonglong2* oA = (ulonglong2*)((ull*)A + j * PTS + 2 * lane);
            ulonglong2* oB = (ulonglong2*)((ull*)B + j * PTS + 2 * lane);
            *oA = make_ulonglong2(h01a[c], h01b[c]);
            *oB = make_ulonglong2(h23a[c], h23b[c]);
        }
    }
    __syncthreads();

    // ---------------- Layer 4: 64 -> 1 (4 dots per point) ----------------
    if (tid < 256) {
        const int q = tid >> 6;            // quantity 0..3
        const int p = tid & 63;            // point
        const float2* hb = (q < 2 ? A : B);
        const bool hi = (q & 1);
        float dot = (q == 0) ? __ldg(&b4[0]) : 0.0f;
        #pragma unroll
        for (int k = 0; k < H3; k++) {
            float2 v = hb[k * PTS + p];
            dot = fmaf(hi ? v.y : v.x, __ldg(&W4[k]), dot);
        }
        out[(blk * PTS + p) * 4 + q] = dot;
    }
}

extern "C" void kernel_launch(void* const* d_in, const int* in_sizes, int n_in,
                              void* d_out, int out_size)
{
    const float* x  = (const float*)d_in[0];
    const float* W1 = (const float*)d_in[1];
    const float* b1 = (const float*)d_in[2];
    const float* W2 = (const float*)d_in[3];
    const float* b2 = (const float*)d_in[4];
    const float* W3 = (const float*)d_in[5];
    const float* b3 = (const float*)d_in[6];
    const float* W4 = (const float*)d_in[7];
    const float* b4 = (const float*)d_in[8];
    float* out = (float*)d_out;

    const int N = in_sizes[0] / 3;  // 262144
    // A(64KB) + B(64KB) + Wdup(64KB) = 192KB
    const int smem_bytes = (2 * H1 * PTS * 2 + 64 * H2 * 2) * (int)sizeof(float);

    cudaFuncSetAttribute(pinn_fused_kernel,
                         cudaFuncAttributeMaxDynamicSharedMemorySize, smem_bytes);

    pinn_fused_kernel<<<N / PTS, TPB, smem_bytes>>>(
        x, W1, b1, W2, b2, W3, b3, W4, b4, out);
}

// round 7
// speedup vs baseline: 1.1602x; 1.1602x over previous
#include <cuda_runtime.h>
#include <math.h>

// PINN forward + forward-mode JVPs (T, dT/dz, dT/dt, d2T/dz2)
// MLP: 3 -> 128 -> 128 -> 64 -> 1, tanh activations.
//
// R7: FFMA2 mainloop, 2 blocks/SM for bubble overlap.
//  - TPB=256 (8 warps), PTS=32, 1 point per thread (lane=point),
//    16 cols per warp. Accumulators: 16 cols x 2 packed quantity-pairs
//    = 32 ull (64 regs).
//  - Activations packed {h,hdz} / {hdt,hdzz} in smem (A,B = 64KB total)
//    -> 2 co-resident blocks per SM; one block's barriers/epilogues
//    overlap the other's FFMA2 mainloop.
//  - Weights via warp-uniform __ldg (L1 broadcast). {w,w} pairs built in
//    4-col sub-blocks to bound live registers. NO mid-loop smem staging
//    (R6's restage-under-live-accumulators spilled to local memory).

#define TPB 256
#define PTS 32           // points per block, 1 per thread
#define H1  128
#define H2  128
#define H3  64

typedef unsigned long long ull;

__device__ __forceinline__ ull ffma2(ull a, ull b, ull c) {
    ull d;
    asm("fma.rn.f32x2 %0, %1, %2, %3;" : "=l"(d) : "l"(a), "l"(b), "l"(c));
    return d;
}
__device__ __forceinline__ ull pack2(float lo, float hi) {
    ull v;
    asm("mov.b64 %0, {%1, %2};" : "=l"(v) : "f"(lo), "f"(hi));
    return v;
}
__device__ __forceinline__ float2 unpack2(ull v) {
    float2 r;
    asm("mov.b64 {%0, %1}, %2;" : "=f"(r.x), "=f"(r.y) : "l"(v));
    return r;
}
// branch-free tanh: 1 - 2/(exp(2u)+1); exact limits at +-inf.
__device__ __forceinline__ float fast_tanh(float u) {
    float e, r;
    asm("ex2.approx.f32 %0, %1;" : "=f"(e) : "f"(u * 2.8853900817779268f));
    asm("rcp.approx.f32 %0, %1;" : "=f"(r) : "f"(e + 1.0f));
    return fmaf(-2.0f, r, 1.0f);
}
// tanh JVP epilogue on packed pairs.
__device__ __forceinline__ void tanh_jvp(ull u01, ull u23, ull* h01, ull* h23) {
    float2 v01 = unpack2(u01);   // x=u, y=u_dz
    float2 v23 = unpack2(u23);   // x=u_dt, y=u_dzz
    float h = fast_tanh(v01.x);
    float s = 1.0f - h * h;
    float hdz  = s * v01.y;
    float hdt  = s * v23.x;
    float hdzz = fmaf(-2.0f * h * hdz, v01.y, s * v23.y);
    *h01 = pack2(h, hdz);
    *h23 = pack2(hdt, hdzz);
}

__global__ __launch_bounds__(TPB, 2)
void pinn_fused_kernel(const float* __restrict__ x,
                       const float* __restrict__ W1, const float* __restrict__ b1,
                       const float* __restrict__ W2, const float* __restrict__ b2,
                       const float* __restrict__ W3, const float* __restrict__ b3,
                       const float* __restrict__ W4, const float* __restrict__ b4,
                       float* __restrict__ out)
{
    extern __shared__ float smem[];
    // A: {h,hdz}[128 units][32 pts] float2 = 32KB
    // B: {hdt,hdzz}[128][32] float2        = 32KB
    float2* A = (float2*)smem;
    float2* B = A + H1 * PTS;

    const int tid  = threadIdx.x;
    const int lane = tid & 31;
    const int warp = tid >> 5;          // 0..7
    const int blk  = blockIdx.x;

    // ---------------- Layer 1: 3 -> 128 (K=3 direct) ----------------
    // pp = lane (fixed per thread), j = warp + it*8
    {
        int pg = blk * PTS + lane;
        float x0 = x[pg * 3 + 0];
        float x1 = x[pg * 3 + 1];
        float x2 = x[pg * 3 + 2];
        #pragma unroll
        for (int it = 0; it < H1 / 8; it++) {
            int j = warp + it * 8;
            float w0 = __ldg(&W1[j]);
            float w1 = __ldg(&W1[H1 + j]);
            float w2 = __ldg(&W1[2 * H1 + j]);
            float u  = fmaf(x0, w0, fmaf(x1, w1, fmaf(x2, w2, __ldg(&b1[j]))));
            float h  = fast_tanh(u);
            float s  = 1.0f - h * h;
            float hdz  = s * w0;
            float hdt  = s * w1;
            float hdzz = -2.0f * h * hdz * w0;
            A[j * PTS + lane] = make_float2(h, hdz);
            B[j * PTS + lane] = make_float2(hdt, hdzz);
        }
    }
    __syncthreads();

    // ---------------- Layer 2: 128 -> 128 (in-place) ----------------
    // 8 warps x 16 cols; 1 point per thread (lane).
    {
        const int j0 = warp * 16;
        ull acc01[16], acc23[16];
        #pragma unroll
        for (int g = 0; g < 4; g++) {
            float4 bb = __ldg(&((const float4*)b2)[j0 / 4 + g]);
            acc01[g * 4 + 0] = pack2(bb.x, 0.0f);
            acc01[g * 4 + 1] = pack2(bb.y, 0.0f);
            acc01[g * 4 + 2] = pack2(bb.z, 0.0f);
            acc01[g * 4 + 3] = pack2(bb.w, 0.0f);
            acc23[g * 4 + 0] = 0ULL; acc23[g * 4 + 1] = 0ULL;
            acc23[g * 4 + 2] = 0ULL; acc23[g * 4 + 3] = 0ULL;
        }
        const ull* aA = (const ull*)A + lane;
        const ull* aB = (const ull*)B + lane;
        #pragma unroll 2
        for (int k = 0; k < H1; k++) {
            ull a01 = aA[k * PTS];
            ull a23 = aB[k * PTS];
            const float4* wrow = (const float4*)(W2 + k * H2 + j0);
            #pragma unroll
            for (int g = 0; g < 4; g++) {
                float4 w = __ldg(&wrow[g]);
                ull wd0 = pack2(w.x, w.x);
                ull wd1 = pack2(w.y, w.y);
                ull wd2 = pack2(w.z, w.z);
                ull wd3 = pack2(w.w, w.w);
                acc01[g*4+0] = ffma2(a01, wd0, acc01[g*4+0]);
                acc23[g*4+0] = ffma2(a23, wd0, acc23[g*4+0]);
                acc01[g*4+1] = ffma2(a01, wd1, acc01[g*4+1]);
                acc23[g*4+1] = ffma2(a23, wd1, acc23[g*4+1]);
                acc01[g*4+2] = ffma2(a01, wd2, acc01[g*4+2]);
                acc23[g*4+2] = ffma2(a23, wd2, acc23[g*4+2]);
                acc01[g*4+3] = ffma2(a01, wd3, acc01[g*4+3]);
                acc23[g*4+3] = ffma2(a23, wd3, acc23[g*4+3]);
            }
        }
        // epilogue in registers
        ull h01[16], h23[16];
        #pragma unroll
        for (int c = 0; c < 16; c++)
            tanh_jvp(acc01[c], acc23[c], &h01[c], &h23[c]);
        __syncthreads();   // all reads of layer-1 activations done
        ull* oA = (ull*)A;
        ull* oB = (ull*)B;
        #pragma unroll
        for (int c = 0; c < 16; c++) {
            int j = j0 + c;
            oA[j * PTS + lane] = h01[c];
            oB[j * PTS + lane] = h23[c];
        }
    }
    __syncthreads();

    // ---------------- Layer 3: 128 -> 64 (in-place) ----------------
    // 8 warps x 8 cols; 1 point per thread.
    {
        const int j0 = warp * 8;
        ull acc01[8], acc23[8];
        #pragma unroll
        for (int g = 0; g < 2; g++) {
            float4 bb = __ldg(&((const float4*)b3)[j0 / 4 + g]);
            acc01[g * 4 + 0] = pack2(bb.x, 0.0f);
            acc01[g * 4 + 1] = pack2(bb.y, 0.0f);
            acc01[g * 4 + 2] = pack2(bb.z, 0.0f);
            acc01[g * 4 + 3] = pack2(bb.w, 0.0f);
            acc23[g * 4 + 0] = 0ULL; acc23[g * 4 + 1] = 0ULL;
            acc23[g * 4 + 2] = 0ULL; acc23[g * 4 + 3] = 0ULL;
        }
        const ull* aA = (const ull*)A + lane;
        const ull* aB = (const ull*)B + lane;
        #pragma unroll 2
        for (int k = 0; k < H2; k++) {
            ull a01 = aA[k * PTS];
            ull a23 = aB[k * PTS];
            const float4* wrow = (const float4*)(W3 + k * H3 + j0);
            #pragma unroll
            for (int g = 0; g < 2; g++) {
                float4 w = __ldg(&wrow[g]);
                ull wd0 = pack2(w.x, w.x);
                ull wd1 = pack2(w.y, w.y);
                ull wd2 = pack2(w.z, w.z);
                ull wd3 = pack2(w.w, w.w);
                acc01[g*4+0] = ffma2(a01, wd0, acc01[g*4+0]);
                acc23[g*4+0] = ffma2(a23, wd0, acc23[g*4+0]);
                acc01[g*4+1] = ffma2(a01, wd1, acc01[g*4+1]);
                acc23[g*4+1] = ffma2(a23, wd1, acc23[g*4+1]);
                acc01[g*4+2] = ffma2(a01, wd2, acc01[g*4+2]);
                acc23[g*4+2] = ffma2(a23, wd2, acc23[g*4+2]);
                acc01[g*4+3] = ffma2(a01, wd3, acc01[g*4+3]);
                acc23[g*4+3] = ffma2(a23, wd3, acc23[g*4+3]);
            }
        }
        ull h01[8], h23[8];
        #pragma unroll
        for (int c = 0; c < 8; c++)
            tanh_jvp(acc01[c], acc23[c], &h01[c], &h23[c]);
        __syncthreads();   // all reads of layer-2 activations done
        ull* oA = (ull*)A;
        ull* oB = (ull*)B;
        #pragma unroll
        for (int c = 0; c < 8; c++) {
            int j = j0 + c;
            oA[j * PTS + lane] = h01[c];
            oB[j * PTS + lane] = h23[c];
        }
    }
    __syncthreads();

    // ---------------- Layer 4: 64 -> 1 (4 dots per point) ----------------
    if (tid < 128) {
        const int q = tid >> 5;            // quantity 0..3
        const int p = tid & 31;            // point
        const float2* hb = (q < 2 ? A : B);
        const bool hi = (q & 1);
        float dot = (q == 0) ? __ldg(&b4[0]) : 0.0f;
        #pragma unroll
        for (int k = 0; k < H3; k++) {
            float2 v = hb[k * PTS + p];
            dot = fmaf(hi ? v.y : v.x, __ldg(&W4[k]), dot);
        }
        out[(blk * PTS + p) * 4 + q] = dot;
    }
}

extern "C" void kernel_launch(void* const* d_in, const int* in_sizes, int n_in,
                              void* d_out, int out_size)
{
    const float* x  = (const float*)d_in[0];
    const float* W1 = (const float*)d_in[1];
    const float* b1 = (const float*)d_in[2];
    const float* W2 = (const float*)d_in[3];
    const float* b2 = (const float*)d_in[4];
    const float* W3 = (const float*)d_in[5];
    const float* b3 = (const float*)d_in[6];
    const float* W4 = (const float*)d_in[7];
    const float* b4 = (const float*)d_in[8];
    float* out = (float*)d_out;

    const int N = in_sizes[0] / 3;  // 262144
    // A(32KB) + B(32KB) = 64KB -> 2 blocks/SM
    const int smem_bytes = 2 * H1 * PTS * (int)sizeof(float2);

    cudaFuncSetAttribute(pinn_fused_kernel,
                         cudaFuncAttributeMaxDynamicSharedMemorySize, smem_bytes);

    pinn_fused_kernel<<<N / PTS, TPB, smem_bytes>>>(
        x, W1, b1, W2, b2, W3, b3, W4, b4, out);
}

// round 8
// speedup vs baseline: 1.1611x; 1.0008x over previous
#include <cuda_runtime.h>
#include <math.h>

// PINN forward + forward-mode JVPs (T, dT/dz, dT/dt, d2T/dz2)
// MLP: 3 -> 128 -> 128 -> 64 -> 1, tanh activations.
//
// R7: FFMA2 mainloop, 2 blocks/SM for bubble overlap.
//  - TPB=256 (8 warps), PTS=32, 1 point per thread (lane=point),
//    16 cols per warp. Accumulators: 16 cols x 2 packed quantity-pairs
//    = 32 ull (64 regs).
//  - Activations packed {h,hdz} / {hdt,hdzz} in smem (A,B = 64KB total)
//    -> 2 co-resident blocks per SM; one block's barriers/epilogues
//    overlap the other's FFMA2 mainloop.
//  - Weights via warp-uniform __ldg (L1 broadcast). {w,w} pairs built in
//    4-col sub-blocks to bound live registers. NO mid-loop smem staging
//    (R6's restage-under-live-accumulators spilled to local memory).

#define TPB 256
#define PTS 32           // points per block, 1 per thread
#define H1  128
#define H2  128
#define H3  64

typedef unsigned long long ull;

__device__ __forceinline__ ull ffma2(ull a, ull b, ull c) {
    ull d;
    asm("fma.rn.f32x2 %0, %1, %2, %3;" : "=l"(d) : "l"(a), "l"(b), "l"(c));
    return d;
}
__device__ __forceinline__ ull pack2(float lo, float hi) {
    ull v;
    asm("mov.b64 %0, {%1, %2};" : "=l"(v) : "f"(lo), "f"(hi));
    return v;
}
__device__ __forceinline__ float2 unpack2(ull v) {
    float2 r;
    asm("mov.b64 {%0, %1}, %2;" : "=f"(r.x), "=f"(r.y) : "l"(v));
    return r;
}
// branch-free tanh: 1 - 2/(exp(2u)+1); exact limits at +-inf.
__device__ __forceinline__ float fast_tanh(float u) {
    float e, r;
    asm("ex2.approx.f32 %0, %1;" : "=f"(e) : "f"(u * 2.8853900817779268f));
    asm("rcp.approx.f32 %0, %1;" : "=f"(r) : "f"(e + 1.0f));
    return fmaf(-2.0f, r, 1.0f);
}
// tanh JVP epilogue on packed pairs.
__device__ __forceinline__ void tanh_jvp(ull u01, ull u23, ull* h01, ull* h23) {
    float2 v01 = unpack2(u01);   // x=u, y=u_dz
    float2 v23 = unpack2(u23);   // x=u_dt, y=u_dzz
    float h = fast_tanh(v01.x);
    float s = 1.0f - h * h;
    float hdz  = s * v01.y;
    float hdt  = s * v23.x;
    float hdzz = fmaf(-2.0f * h * hdz, v01.y, s * v23.y);
    *h01 = pack2(h, hdz);
    *h23 = pack2(hdt, hdzz);
}

__global__ __launch_bounds__(TPB, 2)
void pinn_fused_kernel(const float* __restrict__ x,
                       const float* __restrict__ W1, const float* __restrict__ b1,
                       const float* __restrict__ W2, const float* __restrict__ b2,
                       const float* __restrict__ W3, const float* __restrict__ b3,
                       const float* __restrict__ W4, const float* __restrict__ b4,
                       float* __restrict__ out)
{
    extern __shared__ float smem[];
    // A: {h,hdz}[128 units][32 pts] float2 = 32KB
    // B: {hdt,hdzz}[128][32] float2        = 32KB
    float2* A = (float2*)smem;
    float2* B = A + H1 * PTS;

    const int tid  = threadIdx.x;
    const int lane = tid & 31;
    const int warp = tid >> 5;          // 0..7
    const int blk  = blockIdx.x;

    // ---------------- Layer 1: 3 -> 128 (K=3 direct) ----------------
    // pp = lane (fixed per thread), j = warp + it*8
    {
        int pg = blk * PTS + lane;
        float x0 = x[pg * 3 + 0];
        float x1 = x[pg * 3 + 1];
        float x2 = x[pg * 3 + 2];
        #pragma unroll
        for (int it = 0; it < H1 / 8; it++) {
            int j = warp + it * 8;
            float w0 = __ldg(&W1[j]);
            float w1 = __ldg(&W1[H1 + j]);
            float w2 = __ldg(&W1[2 * H1 + j]);
            float u  = fmaf(x0, w0, fmaf(x1, w1, fmaf(x2, w2, __ldg(&b1[j]))));
            float h  = fast_tanh(u);
            float s  = 1.0f - h * h;
            float hdz  = s * w0;
            float hdt  = s * w1;
            float hdzz = -2.0f * h * hdz * w0;
            A[j * PTS + lane] = make_float2(h, hdz);
            B[j * PTS + lane] = make_float2(hdt, hdzz);
        }
    }
    __syncthreads();

    // ---------------- Layer 2: 128 -> 128 (in-place) ----------------
    // 8 warps x 16 cols; 1 point per thread (lane).
    {
        const int j0 = warp * 16;
        ull acc01[16], acc23[16];
        #pragma unroll
        for (int g = 0; g < 4; g++) {
            float4 bb = __ldg(&((const float4*)b2)[j0 / 4 + g]);
            acc01[g * 4 + 0] = pack2(bb.x, 0.0f);
            acc01[g * 4 + 1] = pack2(bb.y, 0.0f);
            acc01[g * 4 + 2] = pack2(bb.z, 0.0f);
            acc01[g * 4 + 3] = pack2(bb.w, 0.0f);
            acc23[g * 4 + 0] = 0ULL; acc23[g * 4 + 1] = 0ULL;
            acc23[g * 4 + 2] = 0ULL; acc23[g * 4 + 3] = 0ULL;
        }
        const ull* aA = (const ull*)A + lane;
        const ull* aB = (const ull*)B + lane;
        #pragma unroll 2
        for (int k = 0; k < H1; k++) {
            ull a01 = aA[k * PTS];
            ull a23 = aB[k * PTS];
            const float4* wrow = (const float4*)(W2 + k * H2 + j0);
            #pragma unroll
            for (int g = 0; g < 4; g++) {
                float4 w = __ldg(&wrow[g]);
                ull wd0 = pack2(w.x, w.x);
                ull wd1 = pack2(w.y, w.y);
                ull wd2 = pack2(w.z, w.z);
                ull wd3 = pack2(w.w, w.w);
                acc01[g*4+0] = ffma2(a01, wd0, acc01[g*4+0]);
                acc23[g*4+0] = ffma2(a23, wd0, acc23[g*4+0]);
                acc01[g*4+1] = ffma2(a01, wd1, acc01[g*4+1]);
                acc23[g*4+1] = ffma2(a23, wd1, acc23[g*4+1]);
                acc01[g*4+2] = ffma2(a01, wd2, acc01[g*4+2]);
                acc23[g*4+2] = ffma2(a23, wd2, acc23[g*4+2]);
                acc01[g*4+3] = ffma2(a01, wd3, acc01[g*4+3]);
                acc23[g*4+3] = ffma2(a23, wd3, acc23[g*4+3]);
            }
        }
        // epilogue in registers
        ull h01[16], h23[16];
        #pragma unroll
        for (int c = 0; c < 16; c++)
            tanh_jvp(acc01[c], acc23[c], &h01[c], &h23[c]);
        __syncthreads();   // all reads of layer-1 activations done
        ull* oA = (ull*)A;
        ull* oB = (ull*)B;
        #pragma unroll
        for (int c = 0; c < 16; c++) {
            int j = j0 + c;
            oA[j * PTS + lane] = h01[c];
            oB[j * PTS + lane] = h23[c];
        }
    }
    __syncthreads();

    // ---------------- Layer 3: 128 -> 64 (in-place) ----------------
    // 8 warps x 8 cols; 1 point per thread.
    {
        const int j0 = warp * 8;
        ull acc01[8], acc23[8];
        #pragma unroll
        for (int g = 0; g < 2; g++) {
            float4 bb = __ldg(&((const float4*)b3)[j0 / 4 + g]);
            acc01[g * 4 + 0] = pack2(bb.x, 0.0f);
            acc01[g * 4 + 1] = pack2(bb.y, 0.0f);
            acc01[g * 4 + 2] = pack2(bb.z, 0.0f);
            acc01[g * 4 + 3] = pack2(bb.w, 0.0f);
            acc23[g * 4 + 0] = 0ULL; acc23[g * 4 + 1] = 0ULL;
            acc23[g * 4 + 2] = 0ULL; acc23[g * 4 + 3] = 0ULL;
        }
        const ull* aA = (const ull*)A + lane;
        const ull* aB = (const ull*)B + lane;
        #pragma unroll 2
        for (int k = 0; k < H2; k++) {
            ull a01 = aA[k * PTS];
            ull a23 = aB[k * PTS];
            const float4* wrow = (const float4*)(W3 + k * H3 + j0);
            #pragma unroll
            for (int g = 0; g < 2; g++) {
                float4 w = __ldg(&wrow[g]);
                ull wd0 = pack2(w.x, w.x);
                ull wd1 = pack2(w.y, w.y);
                ull wd2 = pack2(w.z, w.z);
                ull wd3 = pack2(w.w, w.w);
                acc01[g*4+0] = ffma2(a01, wd0, acc01[g*4+0]);
                acc23[g*4+0] = ffma2(a23, wd0, acc23[g*4+0]);
                acc01[g*4+1] = ffma2(a01, wd1, acc01[g*4+1]);
                acc23[g*4+1] = ffma2(a23, wd1, acc23[g*4+1]);
                acc01[g*4+2] = ffma2(a01, wd2, acc01[g*4+2]);
                acc23[g*4+2] = ffma2(a23, wd2, acc23[g*4+2]);
                acc01[g*4+3] = ffma2(a01, wd3, acc01[g*4+3]);
                acc23[g*4+3] = ffma2(a23, wd3, acc23[g*4+3]);
            }
        }
        ull h01[8], h23[8];
        #pragma unroll
        for (int c = 0; c < 8; c++)
            tanh_jvp(acc01[c], acc23[c], &h01[c], &h23[c]);
        __syncthreads();   // all reads of layer-2 activations done
        ull* oA = (ull*)A;
        ull* oB = (ull*)B;
        #pragma unroll
        for (int c = 0; c < 8; c++) {
            int j = j0 + c;
            oA[j * PTS + lane] = h01[c];
            oB[j * PTS + lane] = h23[c];
        }
    }
    __syncthreads();

    // ---------------- Layer 4: 64 -> 1 (4 dots per point) ----------------
    if (tid < 128) {
        const int q = tid >> 5;            // quantity 0..3
        const int p = tid & 31;            // point
        const float2* hb = (q < 2 ? A : B);
        const bool hi = (q & 1);
        float dot = (q == 0) ? __ldg(&b4[0]) : 0.0f;
        #pragma unroll
        for (int k = 0; k < H3; k++) {
            float2 v = hb[k * PTS + p];
            dot = fmaf(hi ? v.y : v.x, __ldg(&W4[k]), dot);
        }
        out[(blk * PTS + p) * 4 + q] = dot;
    }
}

extern "C" void kernel_launch(void* const* d_in, const int* in_sizes, int n_in,
                              void* d_out, int out_size)
{
    const float* x  = (const float*)d_in[0];
    const float* W1 = (const float*)d_in[1];
    const float* b1 = (const float*)d_in[2];
    const float* W2 = (const float*)d_in[3];
    const float* b2 = (const float*)d_in[4];
    const float* W3 = (const float*)d_in[5];
    const float* b3 = (const float*)d_in[6];
    const float* W4 = (const float*)d_in[7];
    const float* b4 = (const float*)d_in[8];
    float* out = (float*)d_out;

    const int N = in_sizes[0] / 3;  // 262144
    // A(32KB) + B(32KB) = 64KB -> 2 blocks/SM
    const int smem_bytes = 2 * H1 * PTS * (int)sizeof(float2);

    cudaFuncSetAttribute(pinn_fused_kernel,
                         cudaFuncAttributeMaxDynamicSharedMemorySize, smem_bytes);

    pinn_fused_kernel<<<N / PTS, TPB, smem_bytes>>>(
        x, W1, b1, W2, b2, W3, b3, W4, b4, out);
}